// round 2
// baseline (speedup 1.0000x reference)
#include <cuda_runtime.h>
#include <cuda_bf16.h>
#include <cstdint>

// Problem constants
#define BB 16
#define CC 16
#define PP 256          // patches per image (16x16)
#define DD 4096         // flattened patch dim
#define EE 512          // embedding dim
#define MROWS 4096      // B*P
#define N1 1024         // theta|f concat
#define KSTACK 12288    // 3*DD (hi/lo stacked K)

// ---------------- scratch (device globals; no allocation allowed) ----------------
__device__ __nv_bfloat16 g_p_hi[(size_t)MROWS * DD];
__device__ __nv_bfloat16 g_p_lo[(size_t)MROWS * DD];
__device__ __nv_bfloat16 g_w1t[(size_t)N1 * KSTACK];      // [n, kstack]: Whi | Whi | Wlo
__device__ __nv_bfloat16 g_gwt[(size_t)DD * DD];          // g_w transposed [n, k]
__device__ float g_tf [(size_t)MROWS * N1];               // theta(0:512) | f(512:1024)
__device__ float g_gm [(size_t)MROWS * DD];               // g = p @ g_w
__device__ float g_att[(size_t)BB * PP * PP];             // logits -> softmax weights

__device__ __forceinline__ uint32_t smem_u32(const void* p) {
    uint32_t a;
    asm("{ .reg .u64 t; cvta.to.shared.u64 t, %1; cvt.u32.u64 %0, t; }" : "=r"(a) : "l"(p));
    return a;
}
__device__ __forceinline__ void cp_async16(uint32_t saddr, const void* gptr) {
    asm volatile("cp.async.cg.shared.global [%0], [%1], 16;" :: "r"(saddr), "l"(gptr));
}
__device__ __forceinline__ void cp_commit() {
    asm volatile("cp.async.commit_group;");
}
template <int N>
__device__ __forceinline__ void cp_wait() {
    asm volatile("cp.async.wait_group %0;" :: "n"(N));
}
__device__ __forceinline__ void ldsm_x4(uint32_t* r, uint32_t addr) {
    asm volatile("ldmatrix.sync.aligned.m8n8.x4.shared.b16 {%0,%1,%2,%3}, [%4];"
                 : "=r"(r[0]), "=r"(r[1]), "=r"(r[2]), "=r"(r[3]) : "r"(addr));
}
__device__ __forceinline__ void mma16816(float* d, const uint32_t* a, const uint32_t* b) {
    asm volatile(
        "mma.sync.aligned.m16n8k16.row.col.f32.bf16.bf16.f32 "
        "{%0,%1,%2,%3}, {%4,%5,%6,%7}, {%8,%9}, {%0,%1,%2,%3};"
        : "+f"(d[0]), "+f"(d[1]), "+f"(d[2]), "+f"(d[3])
        : "r"(a[0]), "r"(a[1]), "r"(a[2]), "r"(a[3]), "r"(b[0]), "r"(b[1]));
}

// ---------------- kernel 1: patch extract + bf16 hi/lo split ----------------
__global__ __launch_bounds__(256) void prep_kernel(const float* __restrict__ x) {
    size_t i4 = (size_t)blockIdx.x * 256 + threadIdx.x;
    size_t e0 = i4 << 2;  // element index into p [4096, 4096]
    int d   = (int)(e0 & 4095);
    int row = (int)(e0 >> 12);
    int b = row >> 8, p = row & 255;
    int pi = p >> 4, pj = p & 15;
    int c = d >> 8, rem = d & 255;
    int ih = rem >> 4, iw = rem & 15;
    size_t xi = (((((size_t)b * CC + c) << 8) + (pi << 4) + ih) << 8) + (pj << 4) + iw;
    float4 v = *(const float4*)(x + xi);
    float vv[4] = {v.x, v.y, v.z, v.w};
    __nv_bfloat16 h[4], l[4];
#pragma unroll
    for (int j = 0; j < 4; ++j) {
        h[j] = __float2bfloat16(vv[j]);
        l[j] = __float2bfloat16(vv[j] - __bfloat162float(h[j]));
    }
    ((__nv_bfloat162*)(g_p_hi + e0))[0] = __nv_bfloat162(h[0], h[1]);
    ((__nv_bfloat162*)(g_p_hi + e0))[1] = __nv_bfloat162(h[2], h[3]);
    ((__nv_bfloat162*)(g_p_lo + e0))[0] = __nv_bfloat162(l[0], l[1]);
    ((__nv_bfloat162*)(g_p_lo + e0))[1] = __nv_bfloat162(l[2], l[3]);
}

// ---------------- kernel 2: W1t [1024, 12288] = (theta_w|f_w)^T stacked hi/hi/lo ----------------
__global__ void wsplit1_kernel(const float* __restrict__ theta_w, const float* __restrict__ f_w) {
    __shared__ float s[32][33];
    int k0 = blockIdx.x << 5, n0 = blockIdx.y << 5;
    int tx = threadIdx.x, ty = threadIdx.y;
    int n = n0 + tx;
    float v = (n < EE) ? theta_w[(size_t)(k0 + ty) * EE + n]
                       : f_w[(size_t)(k0 + ty) * EE + (n - EE)];
    s[ty][tx] = v;
    __syncthreads();
    int k = k0 + tx, nn = n0 + ty;
    float w = s[tx][ty];
    __nv_bfloat16 hi = __float2bfloat16(w);
    __nv_bfloat16 lo = __float2bfloat16(w - __bfloat162float(hi));
    size_t base = (size_t)nn * KSTACK + k;
    g_w1t[base]        = hi;
    g_w1t[base + 4096] = hi;
    g_w1t[base + 8192] = lo;
}

// ---------------- kernel 3: g_w transpose -> bf16 ----------------
__global__ void wsplit2_kernel(const float* __restrict__ gw) {
    __shared__ float s[32][33];
    int k0 = blockIdx.x << 5, n0 = blockIdx.y << 5;
    int tx = threadIdx.x, ty = threadIdx.y;
    s[ty][tx] = gw[(size_t)(k0 + ty) * DD + (n0 + tx)];
    __syncthreads();
    g_gwt[(size_t)(n0 + ty) * DD + (k0 + tx)] = __float2bfloat16(s[tx][ty]);
}

// ---------------- kernel 4: HMMA GEMM, C[m,n] = sum_k A[m,k] * Bt[n,k] ----------------
// mode 0: TF = [p_hi|p_lo|p_hi] @ W1t^T  (M=4096, N=1024, K=12288)
// mode 1: g  = p_hi @ gwt^T              (M=4096, N=4096, K=4096)
#define STAGES 3
#define STAGE_BYTES 32768      // A tile 16KB + B tile 16KB
#define GEMM_SMEM (STAGES * STAGE_BYTES)

__global__ __launch_bounds__(256, 2) void gemm_hmma_kernel(int mode) {
    extern __shared__ __align__(1024) char smem[];
    const __nv_bfloat16* __restrict__ Bt;
    float* __restrict__ C;
    int Ktot, Ntot;
    if (mode == 0) { Bt = g_w1t; C = g_tf; Ktot = KSTACK; Ntot = N1; }
    else           { Bt = g_gwt; C = g_gm; Ktot = DD;     Ntot = DD; }
    const int nkb = Ktot >> 6;

    const int tid = threadIdx.x;
    const int lane = tid & 31, wid = tid >> 5;
    const size_t rowM0 = (size_t)blockIdx.y << 7;
    const size_t rowN0 = (size_t)blockIdx.x << 7;
    const uint32_t sbase = smem_u32(smem);

    // loader indexing: 16B chunk per thread, 32 rows per 256-thread pass
    const int chunk = tid & 7;       // 8 chunks of 16B per 128B row
    const int lrow  = tid >> 3;      // 0..31

    auto load_stage = [&](int kb, int slot) {
        int k0 = kb << 6;
        const __nv_bfloat16* Ab = g_p_hi;
        int ka = k0;
        if (mode == 0) { Ab = ((k0 >> 12) == 1) ? g_p_lo : g_p_hi; ka = k0 & 4095; }
        uint32_t sb = sbase + slot * STAGE_BYTES;
#pragma unroll
        for (int rp = 0; rp < 4; ++rp) {
            int r = lrow + (rp << 5);
            int off = (r << 7) + (chunk << 4);
            int sw = off ^ ((off >> 3) & 0x70);
            cp_async16(sb + sw, Ab + (rowM0 + r) * (size_t)DD + ka + (chunk << 3));
            cp_async16(sb + 16384 + sw, Bt + (rowN0 + r) * (size_t)Ktot + k0 + (chunk << 3));
        }
    };

    // warp tiling: 2 (M) x 4 (N) warps; warp tile 64x32
    const int m_off = (wid >> 2) << 6;
    const int n_off = (wid & 3) << 5;
    // per-lane ldmatrix row/col components
    const int arow  = lane & 15;               // + m_off + mt*16
    const int acolb = (lane >> 4) << 4;        // byte col + ks*32
    const int brow  = (lane & 7) + ((lane >> 4) << 3);  // + n_off + ntp*16
    const int bcolb = (lane & 8) << 1;         // byte col + ks*32

    float acc[4][4][4];
#pragma unroll
    for (int i = 0; i < 4; ++i)
#pragma unroll
        for (int j = 0; j < 4; ++j)
#pragma unroll
            for (int q = 0; q < 4; ++q) acc[i][j][q] = 0.f;

    // prologue: stages 0..STAGES-2
#pragma unroll
    for (int s = 0; s < STAGES - 1; ++s) {
        load_stage(s, s);
        cp_commit();
    }

    for (int kb = 0; kb < nkb; ++kb) {
        if (kb + STAGES - 1 < nkb) load_stage(kb + STAGES - 1, (kb + STAGES - 1) % STAGES);
        cp_commit();
        cp_wait<STAGES - 1>();
        __syncthreads();

        uint32_t sA = sbase + (kb % STAGES) * STAGE_BYTES;
        uint32_t sB = sA + 16384;
#pragma unroll
        for (int ks = 0; ks < 4; ++ks) {
            uint32_t afr[4][4], bfr[2][4];
#pragma unroll
            for (int mt = 0; mt < 4; ++mt) {
                int off = ((m_off + (mt << 4) + arow) << 7) + (ks << 5) + acolb;
                ldsm_x4(afr[mt], sA + (off ^ ((off >> 3) & 0x70)));
            }
#pragma unroll
            for (int ntp = 0; ntp < 2; ++ntp) {
                int off = ((n_off + (ntp << 4) + brow) << 7) + (ks << 5) + bcolb;
                ldsm_x4(bfr[ntp], sB + (off ^ ((off >> 3) & 0x70)));
            }
#pragma unroll
            for (int mt = 0; mt < 4; ++mt)
#pragma unroll
                for (int nt = 0; nt < 4; ++nt)
                    mma16816(acc[mt][nt], afr[mt], bfr[nt >> 1] + ((nt & 1) << 1));
        }
        __syncthreads();
    }

    // epilogue: direct stores (float2 per fragment half-row)
#pragma unroll
    for (int mt = 0; mt < 4; ++mt) {
        size_t r0 = rowM0 + m_off + (mt << 4) + (lane >> 2);
#pragma unroll
        for (int nt = 0; nt < 4; ++nt) {
            size_t cix = rowN0 + n_off + (nt << 3) + ((lane & 3) << 1);
            float2 v0 = make_float2(acc[mt][nt][0], acc[mt][nt][1]);
            float2 v1 = make_float2(acc[mt][nt][2], acc[mt][nt][3]);
            *(float2*)(C + r0 * Ntot + cix) = v0;
            *(float2*)(C + (r0 + 8) * Ntot + cix) = v1;
        }
    }
}

// ---------------- kernel 5: logits L[b,p,q] = sum_e (theta+tb)[p,e]*(f+fb)[q,e] (fp32) ----------------
__global__ __launch_bounds__(256) void logits_kernel(const float* __restrict__ theta_b,
                                                     const float* __restrict__ f_b) {
    __shared__ float sT[64][33];
    __shared__ float sF[64][33];
    int b = blockIdx.z;
    int p0 = blockIdx.y << 6, q0 = blockIdx.x << 6;
    int tid = threadIdx.x;
    int tx = tid & 15, ty = tid >> 4;
    float acc[4][4] = {};
    for (int k0 = 0; k0 < EE; k0 += 32) {
        for (int i = tid; i < 64 * 32; i += 256) {
            int rr = i >> 5, e = i & 31;
            sT[rr][e] = g_tf[(size_t)(b * PP + p0 + rr) * N1 + k0 + e] + theta_b[k0 + e];
            sF[rr][e] = g_tf[(size_t)(b * PP + q0 + rr) * N1 + EE + k0 + e] + f_b[k0 + e];
        }
        __syncthreads();
#pragma unroll 4
        for (int e = 0; e < 32; ++e) {
            float a[4], bv[4];
#pragma unroll
            for (int i = 0; i < 4; ++i) a[i] = sT[(ty << 2) + i][e];
#pragma unroll
            for (int j = 0; j < 4; ++j) bv[j] = sF[(tx << 2) + j][e];
#pragma unroll
            for (int i = 0; i < 4; ++i)
#pragma unroll
                for (int j = 0; j < 4; ++j) acc[i][j] = fmaf(a[i], bv[j], acc[i][j]);
        }
        __syncthreads();
    }
#pragma unroll
    for (int i = 0; i < 4; ++i)
#pragma unroll
        for (int j = 0; j < 4; ++j)
            g_att[(size_t)(b * PP + p0 + (ty << 2) + i) * PP + q0 + (tx << 2) + j] = acc[i][j];
}

// ---------------- kernel 6: softmax over rows of 256 ----------------
__global__ __launch_bounds__(256) void softmax_kernel() {
    int row = blockIdx.x, t = threadIdx.x;
    float v = g_att[(size_t)row * PP + t];
    float m = v;
#pragma unroll
    for (int o = 16; o; o >>= 1) m = fmaxf(m, __shfl_xor_sync(0xffffffffu, m, o));
    __shared__ float smax[8], ssum[8];
    if ((t & 31) == 0) smax[t >> 5] = m;
    __syncthreads();
    float M = smax[0];
#pragma unroll
    for (int i = 1; i < 8; ++i) M = fmaxf(M, smax[i]);
    float e = __expf(v - M);
    float s = e;
#pragma unroll
    for (int o = 16; o; o >>= 1) s += __shfl_xor_sync(0xffffffffu, s, o);
    if ((t & 31) == 0) ssum[t >> 5] = s;
    __syncthreads();
    float S = 0.f;
#pragma unroll
    for (int i = 0; i < 8; ++i) S += ssum[i];
    g_att[(size_t)row * PP + t] = e / S;
}

// ---------------- kernel 7: epilogue out = scale * w[b,p,n]*(g+g_b) + x ----------------
__global__ __launch_bounds__(256) void epilogue_kernel(const float* __restrict__ x,
                                                       const float* __restrict__ gb,
                                                       const float* __restrict__ scale,
                                                       float* __restrict__ out) {
    size_t i4 = (size_t)blockIdx.x * 256 + threadIdx.x;
    size_t e0 = i4 << 2;
    int wq = (int)(e0 & 255);
    int h  = (int)((e0 >> 8) & 255);
    int c  = (int)((e0 >> 16) & 15);
    int b  = (int)(e0 >> 20);
    int pi = h >> 4, ih = h & 15, pj = wq >> 4, iw = wq & 15;
    int p = (pi << 4) + pj;
    int n = (ih << 4) + iw;
    size_t rowbp = (size_t)b * PP + p;
    float4 wv = *(const float4*)(g_att + rowbp * PP + n);
    float4 gv = *(const float4*)(g_gm + rowbp * DD + (c << 8) + n);
    float4 gbv = *(const float4*)(gb + (c << 8) + n);
    float4 xv = *(const float4*)(x + e0);
    float s = scale[0];
    float4 o;
    o.x = s * wv.x * (gv.x + gbv.x) + xv.x;
    o.y = s * wv.y * (gv.y + gbv.y) + xv.y;
    o.z = s * wv.z * (gv.z + gbv.z) + xv.z;
    o.w = s * wv.w * (gv.w + gbv.w) + xv.w;
    *(float4*)(out + e0) = o;
}

// ---------------- launcher ----------------
extern "C" void kernel_launch(void* const* d_in, const int* in_sizes, int n_in,
                              void* d_out, int out_size) {
    (void)in_sizes; (void)n_in; (void)out_size;
    const float* x       = (const float*)d_in[0];
    const float* theta_w = (const float*)d_in[1];
    const float* theta_b = (const float*)d_in[2];
    const float* f_w     = (const float*)d_in[3];
    const float* f_b     = (const float*)d_in[4];
    const float* gw      = (const float*)d_in[5];
    const float* gb      = (const float*)d_in[6];
    const float* scale   = (const float*)d_in[7];
    float* out = (float*)d_out;

    cudaFuncSetAttribute(gemm_hmma_kernel,
                         cudaFuncAttributeMaxDynamicSharedMemorySize, GEMM_SMEM);

    prep_kernel<<<16384, 256>>>(x);
    wsplit1_kernel<<<dim3(128, 32), dim3(32, 32)>>>(theta_w, f_w);
    wsplit2_kernel<<<dim3(128, 128), dim3(32, 32)>>>(gw);
    gemm_hmma_kernel<<<dim3(8, 32), 256, GEMM_SMEM>>>(0);   // theta|f, K=12288
    gemm_hmma_kernel<<<dim3(32, 32), 256, GEMM_SMEM>>>(1);  // g, K=4096
    logits_kernel<<<dim3(4, 4, 16), 256>>>(theta_b, f_b);
    softmax_kernel<<<4096, 256>>>();
    epilogue_kernel<<<16384, 256>>>(x, gb, scale, out);
}

// round 4
// speedup vs baseline: 1.1340x; 1.1340x over previous
#include <cuda_runtime.h>
#include <cuda_bf16.h>
#include <cstdint>

// Problem constants
#define BB 16
#define CC 16
#define PP 256          // patches per image (16x16)
#define DD 4096         // flattened patch dim
#define EE 512          // embedding dim
#define MROWS 4096      // B*P
#define N1 1024         // theta|f concat
#define KSTACK 12288    // 3*DD (hi/lo stacked K)

// ---------------- scratch (device globals; no allocation allowed) ----------------
__device__ __nv_bfloat16 g_p_hi[(size_t)MROWS * DD];
__device__ __nv_bfloat16 g_p_lo[(size_t)MROWS * DD];
__device__ __nv_bfloat16 g_w1t[(size_t)N1 * KSTACK];      // [n, kstack]: Whi | Whi | Wlo
__device__ __nv_bfloat16 g_gwt[(size_t)DD * DD];          // g_w transposed [n, k]
__device__ float g_tf [(size_t)MROWS * N1];               // theta(0:512) | f(512:1024)
__device__ float g_gm [(size_t)MROWS * DD];               // g = p @ g_w
__device__ float g_att[(size_t)BB * PP * PP];             // logits -> softmax weights

__device__ __forceinline__ uint32_t smem_u32(const void* p) {
    uint32_t a;
    asm("{ .reg .u64 t; cvta.to.shared.u64 t, %1; cvt.u32.u64 %0, t; }" : "=r"(a) : "l"(p));
    return a;
}
__device__ __forceinline__ void cp_async16(uint32_t saddr, const void* gptr) {
    asm volatile("cp.async.cg.shared.global [%0], [%1], 16;" :: "r"(saddr), "l"(gptr));
}
__device__ __forceinline__ void cp_commit() {
    asm volatile("cp.async.commit_group;");
}
template <int N>
__device__ __forceinline__ void cp_wait() {
    asm volatile("cp.async.wait_group %0;" :: "n"(N));
}
__device__ __forceinline__ void ldsm_x4(uint32_t* r, uint32_t addr) {
    asm volatile("ldmatrix.sync.aligned.m8n8.x4.shared.b16 {%0,%1,%2,%3}, [%4];"
                 : "=r"(r[0]), "=r"(r[1]), "=r"(r[2]), "=r"(r[3]) : "r"(addr));
}
__device__ __forceinline__ void mma16816(float* d, const uint32_t* a, const uint32_t* b) {
    asm volatile(
        "mma.sync.aligned.m16n8k16.row.col.f32.bf16.bf16.f32 "
        "{%0,%1,%2,%3}, {%4,%5,%6,%7}, {%8,%9}, {%0,%1,%2,%3};"
        : "+f"(d[0]), "+f"(d[1]), "+f"(d[2]), "+f"(d[3])
        : "r"(a[0]), "r"(a[1]), "r"(a[2]), "r"(a[3]), "r"(b[0]), "r"(b[1]));
}

// ---------------- kernel 1: patch extract + bf16 hi/lo split ----------------
__global__ __launch_bounds__(256) void prep_kernel(const float* __restrict__ x) {
    size_t i4 = (size_t)blockIdx.x * 256 + threadIdx.x;
    size_t e0 = i4 << 2;  // element index into p [4096, 4096]
    int d   = (int)(e0 & 4095);
    int row = (int)(e0 >> 12);
    int b = row >> 8, p = row & 255;
    int pi = p >> 4, pj = p & 15;
    int c = d >> 8, rem = d & 255;
    int ih = rem >> 4, iw = rem & 15;
    size_t xi = (((((size_t)b * CC + c) << 8) + (pi << 4) + ih) << 8) + (pj << 4) + iw;
    float4 v = *(const float4*)(x + xi);
    float vv[4] = {v.x, v.y, v.z, v.w};
    __nv_bfloat16 h[4], l[4];
#pragma unroll
    for (int j = 0; j < 4; ++j) {
        h[j] = __float2bfloat16(vv[j]);
        l[j] = __float2bfloat16(vv[j] - __bfloat162float(h[j]));
    }
    ((__nv_bfloat162*)(g_p_hi + e0))[0] = __nv_bfloat162(h[0], h[1]);
    ((__nv_bfloat162*)(g_p_hi + e0))[1] = __nv_bfloat162(h[2], h[3]);
    ((__nv_bfloat162*)(g_p_lo + e0))[0] = __nv_bfloat162(l[0], l[1]);
    ((__nv_bfloat162*)(g_p_lo + e0))[1] = __nv_bfloat162(l[2], l[3]);
}

// ---------------- kernel 2: W1t [1024, 12288] = (theta_w|f_w)^T stacked hi/hi/lo ----------------
__global__ void wsplit1_kernel(const float* __restrict__ theta_w, const float* __restrict__ f_w) {
    __shared__ float s[32][33];
    int k0 = blockIdx.x << 5, n0 = blockIdx.y << 5;
    int tx = threadIdx.x, ty = threadIdx.y;
    int n = n0 + tx;
    float v = (n < EE) ? theta_w[(size_t)(k0 + ty) * EE + n]
                       : f_w[(size_t)(k0 + ty) * EE + (n - EE)];
    s[ty][tx] = v;
    __syncthreads();
    int k = k0 + tx, nn = n0 + ty;
    float w = s[tx][ty];
    __nv_bfloat16 hi = __float2bfloat16(w);
    __nv_bfloat16 lo = __float2bfloat16(w - __bfloat162float(hi));
    size_t base = (size_t)nn * KSTACK + k;
    g_w1t[base]        = hi;
    g_w1t[base + 4096] = hi;
    g_w1t[base + 8192] = lo;
}

// ---------------- kernel 3: g_w transpose -> bf16 ----------------
__global__ void wsplit2_kernel(const float* __restrict__ gw) {
    __shared__ float s[32][33];
    int k0 = blockIdx.x << 5, n0 = blockIdx.y << 5;
    int tx = threadIdx.x, ty = threadIdx.y;
    s[ty][tx] = gw[(size_t)(k0 + ty) * DD + (n0 + tx)];
    __syncthreads();
    g_gwt[(size_t)(n0 + ty) * DD + (k0 + tx)] = __float2bfloat16(s[tx][ty]);
}

// ---------------- kernel 4: merged HMMA GEMM, C[m,n] = sum_k A[m,k] * Bt[n,k] ----------------
// bid <  256: TF = [p_hi|p_lo|p_hi] @ W1t^T  (M=4096, N=1024, K=12288)
// bid >= 256: g  = p_hi @ gwt^T              (M=4096, N=4096, K=4096)
#define STAGES 3
#define STAGE_BYTES 32768      // A tile 16KB + B tile 16KB
#define GEMM_SMEM (STAGES * STAGE_BYTES)

__global__ __launch_bounds__(256, 2) void gemm_hmma_kernel() {
    extern __shared__ __align__(1024) char smem[];
    const int bid = blockIdx.x;
    int mode, bx, by;
    if (bid < 256) { mode = 0; bx = bid & 7;  by = bid >> 3; }
    else           { mode = 1; int t = bid - 256; bx = t & 31; by = t >> 5; }

    const __nv_bfloat16* __restrict__ Bt;
    float* __restrict__ C;
    int Ktot, Ntot;
    if (mode == 0) { Bt = g_w1t; C = g_tf; Ktot = KSTACK; Ntot = N1; }
    else           { Bt = g_gwt; C = g_gm; Ktot = DD;     Ntot = DD; }
    const int nkb = Ktot >> 6;

    const int tid = threadIdx.x;
    const int lane = tid & 31, wid = tid >> 5;
    const size_t rowM0 = (size_t)by << 7;
    const size_t rowN0 = (size_t)bx << 7;
    const uint32_t sbase = smem_u32(smem);

    // loader indexing: 16B chunk per thread, 32 rows per 256-thread pass
    const int chunk = tid & 7;       // 8 chunks of 16B per 128B row
    const int lrow  = tid >> 3;      // 0..31

    auto load_stage = [&](int kb, int slot) {
        int k0 = kb << 6;
        const __nv_bfloat16* Ab = g_p_hi;
        int ka = k0;
        if (mode == 0) { Ab = ((k0 >> 12) == 1) ? g_p_lo : g_p_hi; ka = k0 & 4095; }
        uint32_t sb = sbase + slot * STAGE_BYTES;
#pragma unroll
        for (int rp = 0; rp < 4; ++rp) {
            int r = lrow + (rp << 5);
            int off = (r << 7) + (chunk << 4);
            int sw = off ^ ((off >> 3) & 0x70);
            cp_async16(sb + sw, Ab + (rowM0 + r) * (size_t)DD + ka + (chunk << 3));
            cp_async16(sb + 16384 + sw, Bt + (rowN0 + r) * (size_t)Ktot + k0 + (chunk << 3));
        }
    };

    // warp tiling: 2 (M) x 4 (N) warps; warp tile 64x32
    const int m_off = (wid >> 2) << 6;
    const int n_off = (wid & 3) << 5;
    const int arow  = lane & 15;
    const int acolb = (lane >> 4) << 4;
    const int brow  = (lane & 7) + ((lane >> 4) << 3);
    const int bcolb = (lane & 8) << 1;

    float acc[4][4][4];
#pragma unroll
    for (int i = 0; i < 4; ++i)
#pragma unroll
        for (int j = 0; j < 4; ++j)
#pragma unroll
            for (int q = 0; q < 4; ++q) acc[i][j][q] = 0.f;

    // prologue: 2 stages in flight
    load_stage(0, 0); cp_commit();
    load_stage(1, 1); cp_commit();

    for (int kb = 0; kb < nkb; ++kb) {
        cp_wait<1>();            // data for kb resident
        __syncthreads();         // also: all warps done reading slot (kb+2)%3 last iter
        if (kb + 2 < nkb) load_stage(kb + 2, (kb + 2) % STAGES);
        cp_commit();             // always commit (possibly empty) to keep group count

        uint32_t sA = sbase + (kb % STAGES) * STAGE_BYTES;
        uint32_t sB = sA + 16384;
#pragma unroll
        for (int ks = 0; ks < 4; ++ks) {
            uint32_t afr[4][4], bfr[2][4];
#pragma unroll
            for (int mt = 0; mt < 4; ++mt) {
                int off = ((m_off + (mt << 4) + arow) << 7) + (ks << 5) + acolb;
                ldsm_x4(afr[mt], sA + (off ^ ((off >> 3) & 0x70)));
            }
#pragma unroll
            for (int ntp = 0; ntp < 2; ++ntp) {
                int off = ((n_off + (ntp << 4) + brow) << 7) + (ks << 5) + bcolb;
                ldsm_x4(bfr[ntp], sB + (off ^ ((off >> 3) & 0x70)));
            }
#pragma unroll
            for (int mt = 0; mt < 4; ++mt)
#pragma unroll
                for (int nt = 0; nt < 4; ++nt)
                    mma16816(acc[mt][nt], afr[mt], bfr[nt >> 1] + ((nt & 1) << 1));
        }
    }

    // epilogue: direct stores (float2 per fragment half-row)
#pragma unroll
    for (int mt = 0; mt < 4; ++mt) {
        size_t r0 = rowM0 + m_off + (mt << 4) + (lane >> 2);
#pragma unroll
        for (int nt = 0; nt < 4; ++nt) {
            size_t cix = rowN0 + n_off + (nt << 3) + ((lane & 3) << 1);
            float2 v0 = make_float2(acc[mt][nt][0], acc[mt][nt][1]);
            float2 v1 = make_float2(acc[mt][nt][2], acc[mt][nt][3]);
            *(float2*)(C + r0 * Ntot + cix) = v0;
            *(float2*)(C + (r0 + 8) * Ntot + cix) = v1;
        }
    }
}

// ---------------- kernel 5: logits L[b,p,q] = sum_e (theta+tb)[p,e]*(f+fb)[q,e] (fp32) ----------------
__global__ __launch_bounds__(256) void logits_kernel(const float* __restrict__ theta_b,
                                                     const float* __restrict__ f_b) {
    __shared__ float sT[64][33];
    __shared__ float sF[64][33];
    int b = blockIdx.z;
    int p0 = blockIdx.y << 6, q0 = blockIdx.x << 6;
    int tid = threadIdx.x;
    int tx = tid & 15, ty = tid >> 4;
    float acc[4][4] = {};
    for (int k0 = 0; k0 < EE; k0 += 32) {
        for (int i = tid; i < 64 * 32; i += 256) {
            int rr = i >> 5, e = i & 31;
            sT[rr][e] = g_tf[(size_t)(b * PP + p0 + rr) * N1 + k0 + e] + theta_b[k0 + e];
            sF[rr][e] = g_tf[(size_t)(b * PP + q0 + rr) * N1 + EE + k0 + e] + f_b[k0 + e];
        }
        __syncthreads();
#pragma unroll 4
        for (int e = 0; e < 32; ++e) {
            float a[4], bv[4];
#pragma unroll
            for (int i = 0; i < 4; ++i) a[i] = sT[(ty << 2) + i][e];
#pragma unroll
            for (int j = 0; j < 4; ++j) bv[j] = sF[(tx << 2) + j][e];
#pragma unroll
            for (int i = 0; i < 4; ++i)
#pragma unroll
                for (int j = 0; j < 4; ++j) acc[i][j] = fmaf(a[i], bv[j], acc[i][j]);
        }
        __syncthreads();
    }
#pragma unroll
    for (int i = 0; i < 4; ++i)
#pragma unroll
        for (int j = 0; j < 4; ++j)
            g_att[(size_t)(b * PP + p0 + (ty << 2) + i) * PP + q0 + (tx << 2) + j] = acc[i][j];
}

// ---------------- kernel 6: softmax over rows of 256 ----------------
__global__ __launch_bounds__(256) void softmax_kernel() {
    int row = blockIdx.x, t = threadIdx.x;
    float v = g_att[(size_t)row * PP + t];
    float m = v;
#pragma unroll
    for (int o = 16; o; o >>= 1) m = fmaxf(m, __shfl_xor_sync(0xffffffffu, m, o));
    __shared__ float smax[8], ssum[8];
    if ((t & 31) == 0) smax[t >> 5] = m;
    __syncthreads();
    float M = smax[0];
#pragma unroll
    for (int i = 1; i < 8; ++i) M = fmaxf(M, smax[i]);
    float e = __expf(v - M);
    float s = e;
#pragma unroll
    for (int o = 16; o; o >>= 1) s += __shfl_xor_sync(0xffffffffu, s, o);
    if ((t & 31) == 0) ssum[t >> 5] = s;
    __syncthreads();
    float S = 0.f;
#pragma unroll
    for (int i = 0; i < 8; ++i) S += ssum[i];
    g_att[(size_t)row * PP + t] = e / S;
}

// ---------------- kernel 7: epilogue out = scale * w[b,p,n]*(g+g_b) + x ----------------
__global__ __launch_bounds__(256) void epilogue_kernel(const float* __restrict__ x,
                                                       const float* __restrict__ gb,
                                                       const float* __restrict__ scale,
                                                       float* __restrict__ out) {
    size_t i4 = (size_t)blockIdx.x * 256 + threadIdx.x;
    size_t e0 = i4 << 2;
    int wq = (int)(e0 & 255);
    int h  = (int)((e0 >> 8) & 255);
    int c  = (int)((e0 >> 16) & 15);
    int b  = (int)(e0 >> 20);
    int pi = h >> 4, ih = h & 15, pj = wq >> 4, iw = wq & 15;
    int p = (pi << 4) + pj;
    int n = (ih << 4) + iw;
    size_t rowbp = (size_t)b * PP + p;
    float4 wv = *(const float4*)(g_att + rowbp * PP + n);
    float4 gv = *(const float4*)(g_gm + rowbp * DD + (c << 8) + n);
    float4 gbv = *(const float4*)(gb + (c << 8) + n);
    float4 xv = *(const float4*)(x + e0);
    float s = scale[0];
    float4 o;
    o.x = s * wv.x * (gv.x + gbv.x) + xv.x;
    o.y = s * wv.y * (gv.y + gbv.y) + xv.y;
    o.z = s * wv.z * (gv.z + gbv.z) + xv.z;
    o.w = s * wv.w * (gv.w + gbv.w) + xv.w;
    *(float4*)(out + e0) = o;
}

// ---------------- launcher ----------------
extern "C" void kernel_launch(void* const* d_in, const int* in_sizes, int n_in,
                              void* d_out, int out_size) {
    (void)in_sizes; (void)n_in; (void)out_size;
    const float* x       = (const float*)d_in[0];
    const float* theta_w = (const float*)d_in[1];
    const float* theta_b = (const float*)d_in[2];
    const float* f_w     = (const float*)d_in[3];
    const float* f_b     = (const float*)d_in[4];
    const float* gw      = (const float*)d_in[5];
    const float* gb      = (const float*)d_in[6];
    const float* scale   = (const float*)d_in[7];
    float* out = (float*)d_out;

    cudaFuncSetAttribute(gemm_hmma_kernel,
                         cudaFuncAttributeMaxDynamicSharedMemorySize, GEMM_SMEM);

    prep_kernel<<<16384, 256>>>(x);
    wsplit1_kernel<<<dim3(128, 32), dim3(32, 32)>>>(theta_w, f_w);
    wsplit2_kernel<<<dim3(128, 128), dim3(32, 32)>>>(gw);
    gemm_hmma_kernel<<<1280, 256, GEMM_SMEM>>>();   // merged: TF (256 CTAs) + g (1024 CTAs)
    logits_kernel<<<dim3(4, 4, 16), 256>>>(theta_b, f_b);
    softmax_kernel<<<4096, 256>>>();
    epilogue_kernel<<<16384, 256>>>(x, gb, scale, out);
}

// round 5
// speedup vs baseline: 1.1822x; 1.0425x over previous
#include <cuda_runtime.h>
#include <cuda_bf16.h>
#include <cstdint>

// Problem constants
#define BB 16
#define CC 16
#define PP 256          // patches per image (16x16)
#define DD 4096         // flattened patch dim
#define EE 512          // embedding dim
#define MROWS 4096      // B*P
#define N1 1024         // theta|f concat
#define KSTACK 12288    // 3*DD (hi/lo stacked K)

// ---------------- scratch (device globals; no allocation allowed) ----------------
__device__ __nv_bfloat16 g_p_hi[(size_t)MROWS * DD];
__device__ __nv_bfloat16 g_p_lo[(size_t)MROWS * DD];
__device__ __nv_bfloat16 g_w1t[(size_t)N1 * KSTACK];      // [n, kstack]: Whi | Whi | Wlo
__device__ __nv_bfloat16 g_gwt[(size_t)DD * DD];          // g_w transposed [n, k]
__device__ float g_tf [(size_t)MROWS * N1];               // theta(0:512) | f(512:1024)
__device__ float g_gm [(size_t)MROWS * DD];               // g = p @ g_w
__device__ float g_att[(size_t)BB * PP * PP];             // logits -> softmax weights

__device__ __forceinline__ uint32_t smem_u32(const void* p) {
    uint32_t a;
    asm("{ .reg .u64 t; cvta.to.shared.u64 t, %1; cvt.u32.u64 %0, t; }" : "=r"(a) : "l"(p));
    return a;
}
__device__ __forceinline__ void cp_async16(uint32_t saddr, const void* gptr) {
    asm volatile("cp.async.cg.shared.global [%0], [%1], 16;" :: "r"(saddr), "l"(gptr));
}
__device__ __forceinline__ void cp_commit() {
    asm volatile("cp.async.commit_group;");
}
template <int N>
__device__ __forceinline__ void cp_wait() {
    asm volatile("cp.async.wait_group %0;" :: "n"(N));
}
__device__ __forceinline__ void ldsm_x4(uint32_t* r, uint32_t addr) {
    asm volatile("ldmatrix.sync.aligned.m8n8.x4.shared.b16 {%0,%1,%2,%3}, [%4];"
                 : "=r"(r[0]), "=r"(r[1]), "=r"(r[2]), "=r"(r[3]) : "r"(addr));
}
__device__ __forceinline__ void mma16816(float* d, const uint32_t* a, const uint32_t* b) {
    asm volatile(
        "mma.sync.aligned.m16n8k16.row.col.f32.bf16.bf16.f32 "
        "{%0,%1,%2,%3}, {%4,%5,%6,%7}, {%8,%9}, {%0,%1,%2,%3};"
        : "+f"(d[0]), "+f"(d[1]), "+f"(d[2]), "+f"(d[3])
        : "r"(a[0]), "r"(a[1]), "r"(a[2]), "r"(a[3]), "r"(b[0]), "r"(b[1]));
}

// ---------------- kernel 1: patch extract + bf16 hi/lo split ----------------
__global__ __launch_bounds__(256) void prep_kernel(const float* __restrict__ x) {
    size_t i4 = (size_t)blockIdx.x * 256 + threadIdx.x;
    size_t e0 = i4 << 2;  // element index into p [4096, 4096]
    int d   = (int)(e0 & 4095);
    int row = (int)(e0 >> 12);
    int b = row >> 8, p = row & 255;
    int pi = p >> 4, pj = p & 15;
    int c = d >> 8, rem = d & 255;
    int ih = rem >> 4, iw = rem & 15;
    size_t xi = (((((size_t)b * CC + c) << 8) + (pi << 4) + ih) << 8) + (pj << 4) + iw;
    float4 v = *(const float4*)(x + xi);
    float vv[4] = {v.x, v.y, v.z, v.w};
    __nv_bfloat16 h[4], l[4];
#pragma unroll
    for (int j = 0; j < 4; ++j) {
        h[j] = __float2bfloat16(vv[j]);
        l[j] = __float2bfloat16(vv[j] - __bfloat162float(h[j]));
    }
    ((__nv_bfloat162*)(g_p_hi + e0))[0] = __nv_bfloat162(h[0], h[1]);
    ((__nv_bfloat162*)(g_p_hi + e0))[1] = __nv_bfloat162(h[2], h[3]);
    ((__nv_bfloat162*)(g_p_lo + e0))[0] = __nv_bfloat162(l[0], l[1]);
    ((__nv_bfloat162*)(g_p_lo + e0))[1] = __nv_bfloat162(l[2], l[3]);
}

// ---------------- kernel 2: W1t [1024, 12288] = (theta_w|f_w)^T stacked hi/hi/lo ----------------
__global__ void wsplit1_kernel(const float* __restrict__ theta_w, const float* __restrict__ f_w) {
    __shared__ float s[32][33];
    int k0 = blockIdx.x << 5, n0 = blockIdx.y << 5;
    int tx = threadIdx.x, ty = threadIdx.y;
    int n = n0 + tx;
    float v = (n < EE) ? theta_w[(size_t)(k0 + ty) * EE + n]
                       : f_w[(size_t)(k0 + ty) * EE + (n - EE)];
    s[ty][tx] = v;
    __syncthreads();
    int k = k0 + tx, nn = n0 + ty;
    float w = s[tx][ty];
    __nv_bfloat16 hi = __float2bfloat16(w);
    __nv_bfloat16 lo = __float2bfloat16(w - __bfloat162float(hi));
    size_t base = (size_t)nn * KSTACK + k;
    g_w1t[base]        = hi;
    g_w1t[base + 4096] = hi;
    g_w1t[base + 8192] = lo;
}

// ---------------- kernel 3: g_w transpose -> bf16 ----------------
__global__ void wsplit2_kernel(const float* __restrict__ gw) {
    __shared__ float s[32][33];
    int k0 = blockIdx.x << 5, n0 = blockIdx.y << 5;
    int tx = threadIdx.x, ty = threadIdx.y;
    s[ty][tx] = gw[(size_t)(k0 + ty) * DD + (n0 + tx)];
    __syncthreads();
    g_gwt[(size_t)(n0 + ty) * DD + (k0 + tx)] = __float2bfloat16(s[tx][ty]);
}

// ---------------- kernel 4: merged HMMA GEMM, C[m,n] = sum_k A[m,k] * Bt[n,k] ----------------
// 128 threads, 4 warps, warp tile 64x64, CTA tile 128x128, BK=64, 3 stages.
// bid <  256: TF = [p_hi|p_lo|p_hi] @ W1t^T  (M=4096, N=1024, K=12288)
// bid >= 256: g  = p_hi @ gwt^T              (M=4096, N=4096, K=4096)
#define STAGES 3
#define STAGE_BYTES 32768      // A tile 16KB + B tile 16KB
#define GEMM_SMEM (STAGES * STAGE_BYTES)

__global__ __launch_bounds__(128, 2) void gemm_hmma_kernel() {
    extern __shared__ __align__(1024) char smem[];
    const int bid = blockIdx.x;
    int mode, bx, by;
    if (bid < 256) { mode = 0; bx = bid & 7;  by = bid >> 3; }
    else           { mode = 1; int t = bid - 256; bx = t & 31; by = t >> 5; }

    const __nv_bfloat16* __restrict__ Bt;
    float* __restrict__ C;
    int Ktot, Ntot;
    if (mode == 0) { Bt = g_w1t; C = g_tf; Ktot = KSTACK; Ntot = N1; }
    else           { Bt = g_gwt; C = g_gm; Ktot = DD;     Ntot = DD; }
    const int nkb = Ktot >> 6;

    const int tid = threadIdx.x;
    const int lane = tid & 31, wid = tid >> 5;
    const size_t rowM0 = (size_t)by << 7;
    const size_t rowN0 = (size_t)bx << 7;
    const uint32_t sbase = smem_u32(smem);

    // loader indexing: 16B chunk per thread, 16 rows per 128-thread pass
    const int chunk = tid & 7;       // 8 chunks of 16B per 128B row
    const int lrow  = tid >> 3;      // 0..15

    auto load_stage = [&](int kb, int slot) {
        int k0 = kb << 6;
        const __nv_bfloat16* Ab = g_p_hi;
        int ka = k0;
        if (mode == 0) { Ab = ((k0 >> 12) == 1) ? g_p_lo : g_p_hi; ka = k0 & 4095; }
        uint32_t sb = sbase + slot * STAGE_BYTES;
#pragma unroll
        for (int rp = 0; rp < 8; ++rp) {
            int r = lrow + (rp << 4);
            int off = (r << 7) + (chunk << 4);
            int sw = off ^ ((off >> 3) & 0x70);
            cp_async16(sb + sw, Ab + (rowM0 + r) * (size_t)DD + ka + (chunk << 3));
            cp_async16(sb + 16384 + sw, Bt + (rowN0 + r) * (size_t)Ktot + k0 + (chunk << 3));
        }
    };

    // warp tiling: 2 (M) x 2 (N) warps; warp tile 64x64
    const int m_off = (wid & 1) << 6;
    const int n_off = (wid >> 1) << 6;
    const int arow  = lane & 15;
    const int acolb = (lane >> 4) << 4;
    const int brow  = (lane & 7) + ((lane >> 4) << 3);
    const int bcolb = (lane & 8) << 1;

    float acc[4][8][4];
#pragma unroll
    for (int i = 0; i < 4; ++i)
#pragma unroll
        for (int j = 0; j < 8; ++j)
#pragma unroll
            for (int q = 0; q < 4; ++q) acc[i][j][q] = 0.f;

    // prologue: 2 stages in flight
    load_stage(0, 0); cp_commit();
    load_stage(1, 1); cp_commit();

    uint32_t afr[2][4][4], bfr[2][4][4];

    for (int kb = 0; kb < nkb; ++kb) {
        cp_wait<1>();            // data for kb resident
        __syncthreads();         // all warps done reading slot (kb+2)%3 last iter
        if (kb + 2 < nkb) load_stage(kb + 2, (kb + 2) % STAGES);
        cp_commit();             // always commit (possibly empty) to keep group count

        uint32_t sA = sbase + (kb % STAGES) * STAGE_BYTES;
        uint32_t sB = sA + 16384;

        // load ks=0 fragments
#pragma unroll
        for (int mt = 0; mt < 4; ++mt) {
            int off = ((m_off + (mt << 4) + arow) << 7) + acolb;
            ldsm_x4(afr[0][mt], sA + (off ^ ((off >> 3) & 0x70)));
        }
#pragma unroll
        for (int ntp = 0; ntp < 4; ++ntp) {
            int off = ((n_off + (ntp << 4) + brow) << 7) + bcolb;
            ldsm_x4(bfr[0][ntp], sB + (off ^ ((off >> 3) & 0x70)));
        }

#pragma unroll
        for (int ks = 0; ks < 4; ++ks) {
            if (ks < 3) {   // prefetch ks+1 fragments while MMAs of ks run
                int nb = (ks + 1) & 1;
#pragma unroll
                for (int mt = 0; mt < 4; ++mt) {
                    int off = ((m_off + (mt << 4) + arow) << 7) + ((ks + 1) << 5) + acolb;
                    ldsm_x4(afr[nb][mt], sA + (off ^ ((off >> 3) & 0x70)));
                }
#pragma unroll
                for (int ntp = 0; ntp < 4; ++ntp) {
                    int off = ((n_off + (ntp << 4) + brow) << 7) + ((ks + 1) << 5) + bcolb;
                    ldsm_x4(bfr[nb][ntp], sB + (off ^ ((off >> 3) & 0x70)));
                }
            }
            int cb = ks & 1;
#pragma unroll
            for (int mt = 0; mt < 4; ++mt)
#pragma unroll
                for (int nt = 0; nt < 8; ++nt)
                    mma16816(acc[mt][nt], afr[cb][mt], bfr[cb][nt >> 1] + ((nt & 1) << 1));
        }
    }

    // epilogue: direct stores (float2 per fragment half-row)
#pragma unroll
    for (int mt = 0; mt < 4; ++mt) {
        size_t r0 = rowM0 + m_off + (mt << 4) + (lane >> 2);
#pragma unroll
        for (int nt = 0; nt < 8; ++nt) {
            size_t cix = rowN0 + n_off + (nt << 3) + ((lane & 3) << 1);
            float2 v0 = make_float2(acc[mt][nt][0], acc[mt][nt][1]);
            float2 v1 = make_float2(acc[mt][nt][2], acc[mt][nt][3]);
            *(float2*)(C + r0 * Ntot + cix) = v0;
            *(float2*)(C + (r0 + 8) * Ntot + cix) = v1;
        }
    }
}

// ---------------- kernel 5: logits L[b,p,q] = sum_e (theta+tb)[p,e]*(f+fb)[q,e] (fp32) ----------------
__global__ __launch_bounds__(256) void logits_kernel(const float* __restrict__ theta_b,
                                                     const float* __restrict__ f_b) {
    __shared__ float sT[64][33];
    __shared__ float sF[64][33];
    int b = blockIdx.z;
    int p0 = blockIdx.y << 6, q0 = blockIdx.x << 6;
    int tid = threadIdx.x;
    int tx = tid & 15, ty = tid >> 4;
    float acc[4][4] = {};
    for (int k0 = 0; k0 < EE; k0 += 32) {
        for (int i = tid; i < 64 * 32; i += 256) {
            int rr = i >> 5, e = i & 31;
            sT[rr][e] = g_tf[(size_t)(b * PP + p0 + rr) * N1 + k0 + e] + theta_b[k0 + e];
            sF[rr][e] = g_tf[(size_t)(b * PP + q0 + rr) * N1 + EE + k0 + e] + f_b[k0 + e];
        }
        __syncthreads();
#pragma unroll 4
        for (int e = 0; e < 32; ++e) {
            float a[4], bv[4];
#pragma unroll
            for (int i = 0; i < 4; ++i) a[i] = sT[(ty << 2) + i][e];
#pragma unroll
            for (int j = 0; j < 4; ++j) bv[j] = sF[(tx << 2) + j][e];
#pragma unroll
            for (int i = 0; i < 4; ++i)
#pragma unroll
                for (int j = 0; j < 4; ++j) acc[i][j] = fmaf(a[i], bv[j], acc[i][j]);
        }
        __syncthreads();
    }
#pragma unroll
    for (int i = 0; i < 4; ++i)
#pragma unroll
        for (int j = 0; j < 4; ++j)
            g_att[(size_t)(b * PP + p0 + (ty << 2) + i) * PP + q0 + (tx << 2) + j] = acc[i][j];
}

// ---------------- kernel 6: softmax over rows of 256 ----------------
__global__ __launch_bounds__(256) void softmax_kernel() {
    int row = blockIdx.x, t = threadIdx.x;
    float v = g_att[(size_t)row * PP + t];
    float m = v;
#pragma unroll
    for (int o = 16; o; o >>= 1) m = fmaxf(m, __shfl_xor_sync(0xffffffffu, m, o));
    __shared__ float smax[8], ssum[8];
    if ((t & 31) == 0) smax[t >> 5] = m;
    __syncthreads();
    float M = smax[0];
#pragma unroll
    for (int i = 1; i < 8; ++i) M = fmaxf(M, smax[i]);
    float e = __expf(v - M);
    float s = e;
#pragma unroll
    for (int o = 16; o; o >>= 1) s += __shfl_xor_sync(0xffffffffu, s, o);
    if ((t & 31) == 0) ssum[t >> 5] = s;
    __syncthreads();
    float S = 0.f;
#pragma unroll
    for (int i = 0; i < 8; ++i) S += ssum[i];
    g_att[(size_t)row * PP + t] = e / S;
}

// ---------------- kernel 7: epilogue out = scale * w[b,p,n]*(g+g_b) + x ----------------
__global__ __launch_bounds__(256) void epilogue_kernel(const float* __restrict__ x,
                                                       const float* __restrict__ gb,
                                                       const float* __restrict__ scale,
                                                       float* __restrict__ out) {
    size_t i4 = (size_t)blockIdx.x * 256 + threadIdx.x;
    size_t e0 = i4 << 2;
    int wq = (int)(e0 & 255);
    int h  = (int)((e0 >> 8) & 255);
    int c  = (int)((e0 >> 16) & 15);
    int b  = (int)(e0 >> 20);
    int pi = h >> 4, ih = h & 15, pj = wq >> 4, iw = wq & 15;
    int p = (pi << 4) + pj;
    int n = (ih << 4) + iw;
    size_t rowbp = (size_t)b * PP + p;
    float4 wv = *(const float4*)(g_att + rowbp * PP + n);
    float4 gv = *(const float4*)(g_gm + rowbp * DD + (c << 8) + n);
    float4 gbv = *(const float4*)(gb + (c << 8) + n);
    float4 xv = *(const float4*)(x + e0);
    float s = scale[0];
    float4 o;
    o.x = s * wv.x * (gv.x + gbv.x) + xv.x;
    o.y = s * wv.y * (gv.y + gbv.y) + xv.y;
    o.z = s * wv.z * (gv.z + gbv.z) + xv.z;
    o.w = s * wv.w * (gv.w + gbv.w) + xv.w;
    *(float4*)(out + e0) = o;
}

// ---------------- launcher ----------------
extern "C" void kernel_launch(void* const* d_in, const int* in_sizes, int n_in,
                              void* d_out, int out_size) {
    (void)in_sizes; (void)n_in; (void)out_size;
    const float* x       = (const float*)d_in[0];
    const float* theta_w = (const float*)d_in[1];
    const float* theta_b = (const float*)d_in[2];
    const float* f_w     = (const float*)d_in[3];
    const float* f_b     = (const float*)d_in[4];
    const float* gw      = (const float*)d_in[5];
    const float* gb      = (const float*)d_in[6];
    const float* scale   = (const float*)d_in[7];
    float* out = (float*)d_out;

    cudaFuncSetAttribute(gemm_hmma_kernel,
                         cudaFuncAttributeMaxDynamicSharedMemorySize, GEMM_SMEM);

    prep_kernel<<<16384, 256>>>(x);
    wsplit1_kernel<<<dim3(128, 32), dim3(32, 32)>>>(theta_w, f_w);
    wsplit2_kernel<<<dim3(128, 128), dim3(32, 32)>>>(gw);
    gemm_hmma_kernel<<<1280, 128, GEMM_SMEM>>>();   // merged: TF (256 CTAs) + g (1024 CTAs)
    logits_kernel<<<dim3(4, 4, 16), 256>>>(theta_b, f_b);
    softmax_kernel<<<4096, 256>>>();
    epilogue_kernel<<<16384, 256>>>(x, gb, scale, out);
}

// round 9
// speedup vs baseline: 1.2462x; 1.0541x over previous
#include <cuda_runtime.h>
#include <cuda_bf16.h>
#include <cstdint>

// Problem constants
#define BB 16
#define CC 16
#define PP 256          // patches per image (16x16)
#define DD 4096         // flattened patch dim
#define EE 512          // embedding dim
#define MROWS 4096      // B*P
#define N1 1024         // theta|f concat
#define KSTACK 12288    // 3*DD (hi/lo stacked K)
#define NTILES 1280     // 256 (mode0) + 1024 (mode1)

// ---------------- scratch (device globals; no allocation allowed) ----------------
__device__ __nv_bfloat16 g_p_hi[(size_t)MROWS * DD];
__device__ __nv_bfloat16 g_p_lo[(size_t)MROWS * DD];
__device__ __nv_bfloat16 g_w1t[(size_t)N1 * KSTACK];      // [n, kstack]: Whi | Whi | Wlo
__device__ __nv_bfloat16 g_gwt[(size_t)DD * DD];          // g_w transposed [n, k]
__device__ float g_tf [(size_t)MROWS * N1];               // theta(0:512) | f(512:1024)
__device__ __nv_bfloat16 g_gm_bf[(size_t)MROWS * DD];     // g = p @ g_w (bf16)
__device__ float g_att[(size_t)BB * PP * PP];             // logits -> softmax weights
__device__ unsigned int g_tile_ctr;                       // persistent-GEMM work counter

__device__ __forceinline__ uint32_t smem_u32(const void* p) {
    uint32_t a;
    asm("{ .reg .u64 t; cvta.to.shared.u64 t, %1; cvt.u32.u64 %0, t; }" : "=r"(a) : "l"(p));
    return a;
}
__device__ __forceinline__ void cp_async16(uint32_t saddr, const void* gptr) {
    asm volatile("cp.async.cg.shared.global [%0], [%1], 16;" :: "r"(saddr), "l"(gptr));
}
__device__ __forceinline__ void cp_commit() {
    asm volatile("cp.async.commit_group;");
}
template <int N>
__device__ __forceinline__ void cp_wait() {
    asm volatile("cp.async.wait_group %0;" :: "n"(N));
}
__device__ __forceinline__ void ldsm_x4(uint32_t* r, uint32_t addr) {
    asm volatile("ldmatrix.sync.aligned.m8n8.x4.shared.b16 {%0,%1,%2,%3}, [%4];"
                 : "=r"(r[0]), "=r"(r[1]), "=r"(r[2]), "=r"(r[3]) : "r"(addr));
}
__device__ __forceinline__ void mma16816(float* d, const uint32_t* a, const uint32_t* b) {
    asm volatile(
        "mma.sync.aligned.m16n8k16.row.col.f32.bf16.bf16.f32 "
        "{%0,%1,%2,%3}, {%4,%5,%6,%7}, {%8,%9}, {%0,%1,%2,%3};"
        : "+f"(d[0]), "+f"(d[1]), "+f"(d[2]), "+f"(d[3])
        : "r"(a[0]), "r"(a[1]), "r"(a[2]), "r"(a[3]), "r"(b[0]), "r"(b[1]));
}

// ---------------- kernel 1: patch extract + bf16 hi/lo split (+ GEMM counter reset) ----------------
__global__ __launch_bounds__(256) void prep_kernel(const float* __restrict__ x) {
    if (blockIdx.x == 0 && threadIdx.x == 0) g_tile_ctr = 0u;   // reset persistent-GEMM counter
    size_t i4 = (size_t)blockIdx.x * 256 + threadIdx.x;
    size_t e0 = i4 << 2;  // element index into p [4096, 4096]
    int d   = (int)(e0 & 4095);
    int row = (int)(e0 >> 12);
    int b = row >> 8, p = row & 255;
    int pi = p >> 4, pj = p & 15;
    int c = d >> 8, rem = d & 255;
    int ih = rem >> 4, iw = rem & 15;
    size_t xi = (((((size_t)b * CC + c) << 8) + (pi << 4) + ih) << 8) + (pj << 4) + iw;
    float4 v = *(const float4*)(x + xi);
    float vv[4] = {v.x, v.y, v.z, v.w};
    __nv_bfloat16 h[4], l[4];
#pragma unroll
    for (int j = 0; j < 4; ++j) {
        h[j] = __float2bfloat16(vv[j]);
        l[j] = __float2bfloat16(vv[j] - __bfloat162float(h[j]));
    }
    ((__nv_bfloat162*)(g_p_hi + e0))[0] = __nv_bfloat162(h[0], h[1]);
    ((__nv_bfloat162*)(g_p_hi + e0))[1] = __nv_bfloat162(h[2], h[3]);
    ((__nv_bfloat162*)(g_p_lo + e0))[0] = __nv_bfloat162(l[0], l[1]);
    ((__nv_bfloat162*)(g_p_lo + e0))[1] = __nv_bfloat162(l[2], l[3]);
}

// ---------------- kernel 2: W1t [1024, 12288] = (theta_w|f_w)^T stacked hi/hi/lo ----------------
__global__ void wsplit1_kernel(const float* __restrict__ theta_w, const float* __restrict__ f_w) {
    __shared__ float s[32][33];
    int k0 = blockIdx.x << 5, n0 = blockIdx.y << 5;
    int tx = threadIdx.x, ty = threadIdx.y;
    int n = n0 + tx;
    float v = (n < EE) ? theta_w[(size_t)(k0 + ty) * EE + n]
                       : f_w[(size_t)(k0 + ty) * EE + (n - EE)];
    s[ty][tx] = v;
    __syncthreads();
    int k = k0 + tx, nn = n0 + ty;
    float w = s[tx][ty];
    __nv_bfloat16 hi = __float2bfloat16(w);
    __nv_bfloat16 lo = __float2bfloat16(w - __bfloat162float(hi));
    size_t base = (size_t)nn * KSTACK + k;
    g_w1t[base]        = hi;
    g_w1t[base + 4096] = hi;
    g_w1t[base + 8192] = lo;
}

// ---------------- kernel 3: g_w transpose -> bf16 ----------------
__global__ void wsplit2_kernel(const float* __restrict__ gw) {
    __shared__ float s[32][33];
    int k0 = blockIdx.x << 5, n0 = blockIdx.y << 5;
    int tx = threadIdx.x, ty = threadIdx.y;
    s[ty][tx] = gw[(size_t)(k0 + ty) * DD + (n0 + tx)];
    __syncthreads();
    g_gwt[(size_t)(n0 + ty) * DD + (k0 + tx)] = __float2bfloat16(s[tx][ty]);
}

// ---------------- kernel 4: persistent merged HMMA GEMM ----------------
// tile <  256: TF = [p_hi|p_lo|p_hi] @ W1t^T  (M=4096, N=1024, K=12288) -> fp32
// tile >= 256: g  = p_hi @ gwt^T              (M=4096, N=4096, K=4096)  -> bf16
#define STAGES 3
#define STAGE_BYTES 32768      // A tile 16KB + B tile 16KB
#define GEMM_SMEM (STAGES * STAGE_BYTES + 16)

__global__ __launch_bounds__(128, 2) void gemm_hmma_kernel() {
    extern __shared__ __align__(1024) char smem[];
    int* s_tile = (int*)(smem + STAGES * STAGE_BYTES);

    const int tid = threadIdx.x;
    const int lane = tid & 31, wid = tid >> 5;
    const uint32_t sbase = smem_u32(smem);

    const int chunk = tid & 7;       // 8 chunks of 16B per 128B row
    const int lrow  = tid >> 3;      // 0..15

    // warp tiling: 2 (M) x 2 (N) warps; warp tile 64x64
    const int m_off = (wid & 1) << 6;
    const int n_off = (wid >> 1) << 6;
    const int arow  = lane & 15;
    const int acolb = (lane >> 4) << 4;
    const int brow  = (lane & 7) + ((lane >> 4) << 3);
    const int bcolb = (lane & 8) << 1;

    while (true) {
        if (tid == 0) *s_tile = (int)atomicAdd(&g_tile_ctr, 1u);
        __syncthreads();          // broadcast tile id; also fences previous tile's smem reads
        const int t = *s_tile;
        if (t >= NTILES) break;

        int mode, bx, by;
        if (t < 256) { mode = 0; bx = t & 7;  by = t >> 3; }
        else         { int u = t - 256; mode = 1; bx = u & 31; by = u >> 5; }

        const __nv_bfloat16* __restrict__ Bt = (mode == 0) ? g_w1t : g_gwt;
        const int Ktot = (mode == 0) ? KSTACK : DD;
        const int nkb  = Ktot >> 6;
        const size_t rowM0 = (size_t)by << 7;
        const size_t rowN0 = (size_t)bx << 7;

        auto load_stage = [&](int kb, int slot) {
            int k0 = kb << 6;
            const __nv_bfloat16* Ab = g_p_hi;
            int ka = k0;
            if (mode == 0) { Ab = ((k0 >> 12) == 1) ? g_p_lo : g_p_hi; ka = k0 & 4095; }
            uint32_t sb = sbase + slot * STAGE_BYTES;
#pragma unroll
            for (int rp = 0; rp < 8; ++rp) {
                int r = lrow + (rp << 4);
                int off = (r << 7) + (chunk << 4);
                int sw = off ^ ((off >> 3) & 0x70);
                cp_async16(sb + sw, Ab + (rowM0 + r) * (size_t)DD + ka + (chunk << 3));
                cp_async16(sb + 16384 + sw, Bt + (rowN0 + r) * (size_t)Ktot + k0 + (chunk << 3));
            }
        };

        float acc[4][8][4];
#pragma unroll
        for (int i = 0; i < 4; ++i)
#pragma unroll
            for (int j = 0; j < 8; ++j)
#pragma unroll
                for (int q = 0; q < 4; ++q) acc[i][j][q] = 0.f;

        // tile prologue: 2 stages in flight
        load_stage(0, 0); cp_commit();
        load_stage(1, 1); cp_commit();
        cp_wait<1>();        // own group 0 done
        __syncthreads();     // slot 0 visible to all threads

        uint32_t afr[2][4][4], bfr[2][4][4];

        for (int kb = 0; kb < nkb; ++kb) {
            uint32_t sA = sbase + (kb % STAGES) * STAGE_BYTES;
            uint32_t sB = sA + 16384;

            // ks=0 fragments first (slot kb resident+visible); LDS latency hides under cp issue
#pragma unroll
            for (int mt = 0; mt < 4; ++mt) {
                int off = ((m_off + (mt << 4) + arow) << 7) + acolb;
                ldsm_x4(afr[0][mt], sA + (off ^ ((off >> 3) & 0x70)));
            }
#pragma unroll
            for (int ntp = 0; ntp < 4; ++ntp) {
                int off = ((n_off + (ntp << 4) + brow) << 7) + bcolb;
                ldsm_x4(bfr[0][ntp], sB + (off ^ ((off >> 3) & 0x70)));
            }
            if (kb + 2 < nkb) load_stage(kb + 2, (kb + 2) % STAGES);
            cp_commit();

#pragma unroll
            for (int ks = 0; ks < 4; ++ks) {
                if (ks < 3) {   // prefetch ks+1 fragments while MMAs of ks run
                    int nb = (ks + 1) & 1;
#pragma unroll
                    for (int mt = 0; mt < 4; ++mt) {
                        int off = ((m_off + (mt << 4) + arow) << 7) + ((ks + 1) << 5) + acolb;
                        ldsm_x4(afr[nb][mt], sA + (off ^ ((off >> 3) & 0x70)));
                    }
#pragma unroll
                    for (int ntp = 0; ntp < 4; ++ntp) {
                        int off = ((n_off + (ntp << 4) + brow) << 7) + ((ks + 1) << 5) + bcolb;
                        ldsm_x4(bfr[nb][ntp], sB + (off ^ ((off >> 3) & 0x70)));
                    }
                }
                int cb = ks & 1;
#pragma unroll
                for (int mt = 0; mt < 4; ++mt)
#pragma unroll
                    for (int nt = 0; nt < 8; ++nt)
                        mma16816(acc[mt][nt], afr[cb][mt], bfr[cb][nt >> 1] + ((nt & 1) << 1));
            }

            cp_wait<1>();      // group kb+1 done (only just-committed group may pend)
            __syncthreads();   // slot kb+1 visible; readers done before next overwrite
        }

        // epilogue
        if (mode == 0) {
#pragma unroll
            for (int mt = 0; mt < 4; ++mt) {
                size_t r0 = rowM0 + m_off + (mt << 4) + (lane >> 2);
#pragma unroll
                for (int nt = 0; nt < 8; ++nt) {
                    size_t cix = rowN0 + n_off + (nt << 3) + ((lane & 3) << 1);
                    *(float2*)(g_tf + r0 * N1 + cix) = make_float2(acc[mt][nt][0], acc[mt][nt][1]);
                    *(float2*)(g_tf + (r0 + 8) * N1 + cix) = make_float2(acc[mt][nt][2], acc[mt][nt][3]);
                }
            }
        } else {
#pragma unroll
            for (int mt = 0; mt < 4; ++mt) {
                size_t r0 = rowM0 + m_off + (mt << 4) + (lane >> 2);
#pragma unroll
                for (int nt = 0; nt < 8; ++nt) {
                    size_t cix = rowN0 + n_off + (nt << 3) + ((lane & 3) << 1);
                    *(__nv_bfloat162*)(g_gm_bf + r0 * DD + cix) =
                        __nv_bfloat162(__float2bfloat16(acc[mt][nt][0]), __float2bfloat16(acc[mt][nt][1]));
                    *(__nv_bfloat162*)(g_gm_bf + (r0 + 8) * DD + cix) =
                        __nv_bfloat162(__float2bfloat16(acc[mt][nt][2]), __float2bfloat16(acc[mt][nt][3]));
                }
            }
        }
    }
}

// ---------------- kernel 5: logits L[b,p,q] = sum_e (theta+tb)[p,e]*(f+fb)[q,e] (fp32) ----------------
__global__ __launch_bounds__(256) void logits_kernel(const float* __restrict__ theta_b,
                                                     const float* __restrict__ f_b) {
    __shared__ float sT[64][33];
    __shared__ float sF[64][33];
    int b = blockIdx.z;
    int p0 = blockIdx.y << 6, q0 = blockIdx.x << 6;
    int tid = threadIdx.x;
    int tx = tid & 15, ty = tid >> 4;
    float acc[4][4] = {};
    for (int k0 = 0; k0 < EE; k0 += 32) {
        for (int i = tid; i < 64 * 32; i += 256) {
            int rr = i >> 5, e = i & 31;
            sT[rr][e] = g_tf[(size_t)(b * PP + p0 + rr) * N1 + k0 + e] + theta_b[k0 + e];
            sF[rr][e] = g_tf[(size_t)(b * PP + q0 + rr) * N1 + EE + k0 + e] + f_b[k0 + e];
        }
        __syncthreads();
#pragma unroll 4
        for (int e = 0; e < 32; ++e) {
            float a[4], bv[4];
#pragma unroll
            for (int i = 0; i < 4; ++i) a[i] = sT[(ty << 2) + i][e];
#pragma unroll
            for (int j = 0; j < 4; ++j) bv[j] = sF[(tx << 2) + j][e];
#pragma unroll
            for (int i = 0; i < 4; ++i)
#pragma unroll
                for (int j = 0; j < 4; ++j) acc[i][j] = fmaf(a[i], bv[j], acc[i][j]);
        }
        __syncthreads();
    }
#pragma unroll
    for (int i = 0; i < 4; ++i)
#pragma unroll
        for (int j = 0; j < 4; ++j)
            g_att[(size_t)(b * PP + p0 + (ty << 2) + i) * PP + q0 + (tx << 2) + j] = acc[i][j];
}

// ---------------- kernel 6: softmax over rows of 256 ----------------
__global__ __launch_bounds__(256) void softmax_kernel() {
    int row = blockIdx.x, t = threadIdx.x;
    float v = g_att[(size_t)row * PP + t];
    float m = v;
#pragma unroll
    for (int o = 16; o; o >>= 1) m = fmaxf(m, __shfl_xor_sync(0xffffffffu, m, o));
    __shared__ float smax[8], ssum[8];
    if ((t & 31) == 0) smax[t >> 5] = m;
    __syncthreads();
    float M = smax[0];
#pragma unroll
    for (int i = 1; i < 8; ++i) M = fmaxf(M, smax[i]);
    float e = __expf(v - M);
    float s = e;
#pragma unroll
    for (int o = 16; o; o >>= 1) s += __shfl_xor_sync(0xffffffffu, s, o);
    if ((t & 31) == 0) ssum[t >> 5] = s;
    __syncthreads();
    float S = 0.f;
#pragma unroll
    for (int i = 0; i < 8; ++i) S += ssum[i];
    g_att[(size_t)row * PP + t] = e / S;
}

// ---------------- kernel 7: epilogue out = scale * w[b,p,n]*(g+g_b) + x ----------------
__global__ __launch_bounds__(256) void epilogue_kernel(const float* __restrict__ x,
                                                       const float* __restrict__ gb,
                                                       const float* __restrict__ scale,
                                                       float* __restrict__ out) {
    size_t i4 = (size_t)blockIdx.x * 256 + threadIdx.x;
    size_t e0 = i4 << 2;
    int wq = (int)(e0 & 255);
    int h  = (int)((e0 >> 8) & 255);
    int c  = (int)((e0 >> 16) & 15);
    int b  = (int)(e0 >> 20);
    int pi = h >> 4, ih = h & 15, pj = wq >> 4, iw = wq & 15;
    int p = (pi << 4) + pj;
    int n = (ih << 4) + iw;
    size_t rowbp = (size_t)b * PP + p;
    float4 wv = *(const float4*)(g_att + rowbp * PP + n);
    __nv_bfloat162 gv01 = ((const __nv_bfloat162*)(g_gm_bf + rowbp * DD + (c << 8) + n))[0];
    __nv_bfloat162 gv23 = ((const __nv_bfloat162*)(g_gm_bf + rowbp * DD + (c << 8) + n))[1];
    float4 gbv = *(const float4*)(gb + (c << 8) + n);
    float4 xv = *(const float4*)(x + e0);
    float s = scale[0];
    float4 o;
    o.x = s * wv.x * (__bfloat162float(gv01.x) + gbv.x) + xv.x;
    o.y = s * wv.y * (__bfloat162float(gv01.y) + gbv.y) + xv.y;
    o.z = s * wv.z * (__bfloat162float(gv23.x) + gbv.z) + xv.z;
    o.w = s * wv.w * (__bfloat162float(gv23.y) + gbv.w) + xv.w;
    *(float4*)(out + e0) = o;
}

// ---------------- launcher ----------------
extern "C" void kernel_launch(void* const* d_in, const int* in_sizes, int n_in,
                              void* d_out, int out_size) {
    (void)in_sizes; (void)n_in; (void)out_size;
    const float* x       = (const float*)d_in[0];
    const float* theta_w = (const float*)d_in[1];
    const float* theta_b = (const float*)d_in[2];
    const float* f_w     = (const float*)d_in[3];
    const float* f_b     = (const float*)d_in[4];
    const float* gw      = (const float*)d_in[5];
    const float* gb      = (const float*)d_in[6];
    const float* scale   = (const float*)d_in[7];
    float* out = (float*)d_out;

    cudaFuncSetAttribute(gemm_hmma_kernel,
                         cudaFuncAttributeMaxDynamicSharedMemorySize, GEMM_SMEM);

    prep_kernel<<<16384, 256>>>(x);                         // also resets g_tile_ctr
    wsplit1_kernel<<<dim3(128, 32), dim3(32, 32)>>>(theta_w, f_w);
    wsplit2_kernel<<<dim3(128, 128), dim3(32, 32)>>>(gw);
    gemm_hmma_kernel<<<304, 128, GEMM_SMEM>>>();            // persistent, dynamic tiles
    logits_kernel<<<dim3(4, 4, 16), 256>>>(theta_b, f_b);
    softmax_kernel<<<4096, 256>>>();
    epilogue_kernel<<<16384, 256>>>(x, gb, scale, out);
}

// round 10
// speedup vs baseline: 1.3714x; 1.1004x over previous
#include <cuda_runtime.h>
#include <cuda_bf16.h>
#include <cstdint>

// Problem constants
#define BB 16
#define CC 16
#define PP 256          // patches per image (16x16)
#define DD 4096         // flattened patch dim
#define EE 512          // embedding dim
#define MROWS 4096      // B*P
#define N1 1024         // theta|f concat
#define KSTACK 12288    // 3*DD (hi/lo stacked K)
#define KLOG 1536       // 3*EE (hi/lo stacked logits K)
#define NTILES 1280     // 256 (mode0) + 1024 (mode1)

// ---------------- scratch (device globals; no allocation allowed) ----------------
__device__ __nv_bfloat16 g_p_hi[(size_t)MROWS * DD];
__device__ __nv_bfloat16 g_p_lo[(size_t)MROWS * DD];
__device__ __nv_bfloat16 g_w1t[(size_t)N1 * KSTACK];      // [n, kstack]: Whi | Whi | Wlo
__device__ __nv_bfloat16 g_gwt[(size_t)DD * DD];          // g_w transposed [n, k]
__device__ float g_tf [(size_t)MROWS * N1];               // theta(0:512) | f(512:1024)
__device__ __nv_bfloat16 g_lA[(size_t)MROWS * KLOG];      // [thetahi | thetalo | thetahi] (+bias)
__device__ __nv_bfloat16 g_lB[(size_t)MROWS * KLOG];      // [fhi | fhi | flo] (+bias)
__device__ __nv_bfloat16 g_gm_bf[(size_t)MROWS * DD];     // g = p @ g_w (bf16)
__device__ float g_att[(size_t)BB * PP * PP];             // logits -> softmax weights
__device__ unsigned int g_tile_ctr;                       // persistent-GEMM work counter

__device__ __forceinline__ uint32_t smem_u32(const void* p) {
    uint32_t a;
    asm("{ .reg .u64 t; cvta.to.shared.u64 t, %1; cvt.u32.u64 %0, t; }" : "=r"(a) : "l"(p));
    return a;
}
__device__ __forceinline__ void cp_async16(uint32_t saddr, const void* gptr) {
    asm volatile("cp.async.cg.shared.global [%0], [%1], 16;" :: "r"(saddr), "l"(gptr));
}
__device__ __forceinline__ void cp_commit() {
    asm volatile("cp.async.commit_group;");
}
template <int N>
__device__ __forceinline__ void cp_wait() {
    asm volatile("cp.async.wait_group %0;" :: "n"(N));
}
__device__ __forceinline__ void ldsm_x4(uint32_t* r, uint32_t addr) {
    asm volatile("ldmatrix.sync.aligned.m8n8.x4.shared.b16 {%0,%1,%2,%3}, [%4];"
                 : "=r"(r[0]), "=r"(r[1]), "=r"(r[2]), "=r"(r[3]) : "r"(addr));
}
__device__ __forceinline__ void mma16816(float* d, const uint32_t* a, const uint32_t* b) {
    asm volatile(
        "mma.sync.aligned.m16n8k16.row.col.f32.bf16.bf16.f32 "
        "{%0,%1,%2,%3}, {%4,%5,%6,%7}, {%8,%9}, {%0,%1,%2,%3};"
        : "+f"(d[0]), "+f"(d[1]), "+f"(d[2]), "+f"(d[3])
        : "r"(a[0]), "r"(a[1]), "r"(a[2]), "r"(a[3]), "r"(b[0]), "r"(b[1]));
}

// ---------------- kernel 1: patch extract + bf16 hi/lo split (+ GEMM counter reset) ----------------
__global__ __launch_bounds__(256) void prep_kernel(const float* __restrict__ x) {
    if (blockIdx.x == 0 && threadIdx.x == 0) g_tile_ctr = 0u;   // reset persistent-GEMM counter
    size_t i4 = (size_t)blockIdx.x * 256 + threadIdx.x;
    size_t e0 = i4 << 2;  // element index into p [4096, 4096]
    int d   = (int)(e0 & 4095);
    int row = (int)(e0 >> 12);
    int b = row >> 8, p = row & 255;
    int pi = p >> 4, pj = p & 15;
    int c = d >> 8, rem = d & 255;
    int ih = rem >> 4, iw = rem & 15;
    size_t xi = (((((size_t)b * CC + c) << 8) + (pi << 4) + ih) << 8) + (pj << 4) + iw;
    float4 v = *(const float4*)(x + xi);
    float vv[4] = {v.x, v.y, v.z, v.w};
    __nv_bfloat16 h[4], l[4];
#pragma unroll
    for (int j = 0; j < 4; ++j) {
        h[j] = __float2bfloat16(vv[j]);
        l[j] = __float2bfloat16(vv[j] - __bfloat162float(h[j]));
    }
    ((__nv_bfloat162*)(g_p_hi + e0))[0] = __nv_bfloat162(h[0], h[1]);
    ((__nv_bfloat162*)(g_p_hi + e0))[1] = __nv_bfloat162(h[2], h[3]);
    ((__nv_bfloat162*)(g_p_lo + e0))[0] = __nv_bfloat162(l[0], l[1]);
    ((__nv_bfloat162*)(g_p_lo + e0))[1] = __nv_bfloat162(l[2], l[3]);
}

// ---------------- kernel 2: W1t [1024, 12288] = (theta_w|f_w)^T stacked hi/hi/lo ----------------
__global__ void wsplit1_kernel(const float* __restrict__ theta_w, const float* __restrict__ f_w) {
    __shared__ float s[32][33];
    int k0 = blockIdx.x << 5, n0 = blockIdx.y << 5;
    int tx = threadIdx.x, ty = threadIdx.y;
    int n = n0 + tx;
    float v = (n < EE) ? theta_w[(size_t)(k0 + ty) * EE + n]
                       : f_w[(size_t)(k0 + ty) * EE + (n - EE)];
    s[ty][tx] = v;
    __syncthreads();
    int k = k0 + tx, nn = n0 + ty;
    float w = s[tx][ty];
    __nv_bfloat16 hi = __float2bfloat16(w);
    __nv_bfloat16 lo = __float2bfloat16(w - __bfloat162float(hi));
    size_t base = (size_t)nn * KSTACK + k;
    g_w1t[base]        = hi;
    g_w1t[base + 4096] = hi;
    g_w1t[base + 8192] = lo;
}

// ---------------- kernel 3: g_w transpose -> bf16 ----------------
__global__ void wsplit2_kernel(const float* __restrict__ gw) {
    __shared__ float s[32][33];
    int k0 = blockIdx.x << 5, n0 = blockIdx.y << 5;
    int tx = threadIdx.x, ty = threadIdx.y;
    s[ty][tx] = gw[(size_t)(k0 + ty) * DD + (n0 + tx)];
    __syncthreads();
    g_gwt[(size_t)(n0 + ty) * DD + (k0 + tx)] = __float2bfloat16(s[tx][ty]);
}

// ---------------- kernel 4: persistent merged HMMA GEMM ----------------
// tile <  256: TF = [p_hi|p_lo|p_hi] @ W1t^T  (M=4096, N=1024, K=12288) -> fp32
// tile >= 256: g  = p_hi @ gwt^T              (M=4096, N=4096, K=4096)  -> bf16
#define STAGES 3
#define STAGE_BYTES 32768      // A tile 16KB + B tile 16KB
#define GEMM_SMEM (STAGES * STAGE_BYTES + 16)

__global__ __launch_bounds__(128, 2) void gemm_hmma_kernel() {
    extern __shared__ __align__(1024) char smem[];
    int* s_tile = (int*)(smem + STAGES * STAGE_BYTES);

    const int tid = threadIdx.x;
    const int lane = tid & 31, wid = tid >> 5;
    const uint32_t sbase = smem_u32(smem);

    const int chunk = tid & 7;       // 8 chunks of 16B per 128B row
    const int lrow  = tid >> 3;      // 0..15

    // warp tiling: 2 (M) x 2 (N) warps; warp tile 64x64
    const int m_off = (wid & 1) << 6;
    const int n_off = (wid >> 1) << 6;
    const int arow  = lane & 15;
    const int acolb = (lane >> 4) << 4;
    const int brow  = (lane & 7) + ((lane >> 4) << 3);
    const int bcolb = (lane & 8) << 1;

    while (true) {
        if (tid == 0) *s_tile = (int)atomicAdd(&g_tile_ctr, 1u);
        __syncthreads();          // broadcast tile id; also fences previous tile's smem reads
        const int t = *s_tile;
        if (t >= NTILES) break;

        int mode, bx, by;
        if (t < 256) { mode = 0; bx = t & 7;  by = t >> 3; }
        else         { int u = t - 256; mode = 1; bx = u & 31; by = u >> 5; }

        const __nv_bfloat16* __restrict__ Bt = (mode == 0) ? g_w1t : g_gwt;
        const int Ktot = (mode == 0) ? KSTACK : DD;
        const int nkb  = Ktot >> 6;
        const size_t rowM0 = (size_t)by << 7;
        const size_t rowN0 = (size_t)bx << 7;

        auto load_stage = [&](int kb, int slot) {
            int k0 = kb << 6;
            const __nv_bfloat16* Ab = g_p_hi;
            int ka = k0;
            if (mode == 0) { Ab = ((k0 >> 12) == 1) ? g_p_lo : g_p_hi; ka = k0 & 4095; }
            uint32_t sb = sbase + slot * STAGE_BYTES;
#pragma unroll
            for (int rp = 0; rp < 8; ++rp) {
                int r = lrow + (rp << 4);
                int off = (r << 7) + (chunk << 4);
                int sw = off ^ ((off >> 3) & 0x70);
                cp_async16(sb + sw, Ab + (rowM0 + r) * (size_t)DD + ka + (chunk << 3));
                cp_async16(sb + 16384 + sw, Bt + (rowN0 + r) * (size_t)Ktot + k0 + (chunk << 3));
            }
        };

        float acc[4][8][4];
#pragma unroll
        for (int i = 0; i < 4; ++i)
#pragma unroll
            for (int j = 0; j < 8; ++j)
#pragma unroll
                for (int q = 0; q < 4; ++q) acc[i][j][q] = 0.f;

        // tile prologue: 2 stages in flight
        load_stage(0, 0); cp_commit();
        load_stage(1, 1); cp_commit();
        cp_wait<1>();        // own group 0 done
        __syncthreads();     // slot 0 visible to all threads

        uint32_t afr[2][4][4], bfr[2][4][4];

        for (int kb = 0; kb < nkb; ++kb) {
            uint32_t sA = sbase + (kb % STAGES) * STAGE_BYTES;
            uint32_t sB = sA + 16384;

            // ks=0 fragments first (slot kb resident+visible); LDS latency hides under cp issue
#pragma unroll
            for (int mt = 0; mt < 4; ++mt) {
                int off = ((m_off + (mt << 4) + arow) << 7) + acolb;
                ldsm_x4(afr[0][mt], sA + (off ^ ((off >> 3) & 0x70)));
            }
#pragma unroll
            for (int ntp = 0; ntp < 4; ++ntp) {
                int off = ((n_off + (ntp << 4) + brow) << 7) + bcolb;
                ldsm_x4(bfr[0][ntp], sB + (off ^ ((off >> 3) & 0x70)));
            }
            if (kb + 2 < nkb) load_stage(kb + 2, (kb + 2) % STAGES);
            cp_commit();

            // ks = 0..2 with fragment prefetch; all smem reads of slot kb done by end of ks=2
#pragma unroll
            for (int ks = 0; ks < 3; ++ks) {
                int nb = (ks + 1) & 1;
#pragma unroll
                for (int mt = 0; mt < 4; ++mt) {
                    int off = ((m_off + (mt << 4) + arow) << 7) + ((ks + 1) << 5) + acolb;
                    ldsm_x4(afr[nb][mt], sA + (off ^ ((off >> 3) & 0x70)));
                }
#pragma unroll
                for (int ntp = 0; ntp < 4; ++ntp) {
                    int off = ((n_off + (ntp << 4) + brow) << 7) + ((ks + 1) << 5) + bcolb;
                    ldsm_x4(bfr[nb][ntp], sB + (off ^ ((off >> 3) & 0x70)));
                }
                int cb = ks & 1;
#pragma unroll
                for (int mt = 0; mt < 4; ++mt)
#pragma unroll
                    for (int nt = 0; nt < 8; ++nt)
                        mma16816(acc[mt][nt], afr[cb][mt], bfr[cb][nt >> 1] + ((nt & 1) << 1));
            }

            // barrier BEFORE the last (register-only) MMA group: 32 MMAs hide barrier release
            cp_wait<1>();      // group kb+1 done (only just-committed group may pend)
            __syncthreads();   // slot kb+1 visible; slot kb readers all done (pre-barrier)
#pragma unroll
            for (int mt = 0; mt < 4; ++mt)
#pragma unroll
                for (int nt = 0; nt < 8; ++nt)
                    mma16816(acc[mt][nt], afr[1][mt], bfr[1][nt >> 1] + ((nt & 1) << 1));
        }

        // epilogue
        if (mode == 0) {
#pragma unroll
            for (int mt = 0; mt < 4; ++mt) {
                size_t r0 = rowM0 + m_off + (mt << 4) + (lane >> 2);
#pragma unroll
                for (int nt = 0; nt < 8; ++nt) {
                    size_t cix = rowN0 + n_off + (nt << 3) + ((lane & 3) << 1);
                    *(float2*)(g_tf + r0 * N1 + cix) = make_float2(acc[mt][nt][0], acc[mt][nt][1]);
                    *(float2*)(g_tf + (r0 + 8) * N1 + cix) = make_float2(acc[mt][nt][2], acc[mt][nt][3]);
                }
            }
        } else {
#pragma unroll
            for (int mt = 0; mt < 4; ++mt) {
                size_t r0 = rowM0 + m_off + (mt << 4) + (lane >> 2);
#pragma unroll
                for (int nt = 0; nt < 8; ++nt) {
                    size_t cix = rowN0 + n_off + (nt << 3) + ((lane & 3) << 1);
                    *(__nv_bfloat162*)(g_gm_bf + r0 * DD + cix) =
                        __nv_bfloat162(__float2bfloat16(acc[mt][nt][0]), __float2bfloat16(acc[mt][nt][1]));
                    *(__nv_bfloat162*)(g_gm_bf + (r0 + 8) * DD + cix) =
                        __nv_bfloat162(__float2bfloat16(acc[mt][nt][2]), __float2bfloat16(acc[mt][nt][3]));
                }
            }
        }
    }
}

// ---------------- kernel 5: theta/f hi/lo split (+bias) for tensor-core logits ----------------
// g_lA row = [thetahi | thetalo | thetahi], g_lB row = [fhi | fhi | flo]
__global__ __launch_bounds__(256) void tfsplit_kernel(const float* __restrict__ theta_b,
                                                      const float* __restrict__ f_b) {
    size_t idx = (size_t)blockIdx.x * 256 + threadIdx.x;   // 4096*128 = 524288 threads
    size_t row = idx >> 7;
    int e0 = (int)(idx & 127) << 2;                        // 0..508
    float4 th = *(const float4*)(g_tf + row * N1 + e0);
    float4 ff = *(const float4*)(g_tf + row * N1 + EE + e0);
    float4 tb = *(const float4*)(theta_b + e0);
    float4 fb = *(const float4*)(f_b + e0);
    float tv[4] = {th.x + tb.x, th.y + tb.y, th.z + tb.z, th.w + tb.w};
    float fv[4] = {ff.x + fb.x, ff.y + fb.y, ff.z + fb.z, ff.w + fb.w};
    __nv_bfloat16 thi[4], tlo[4], fhi[4], flo[4];
#pragma unroll
    for (int j = 0; j < 4; ++j) {
        thi[j] = __float2bfloat16(tv[j]);
        tlo[j] = __float2bfloat16(tv[j] - __bfloat162float(thi[j]));
        fhi[j] = __float2bfloat16(fv[j]);
        flo[j] = __float2bfloat16(fv[j] - __bfloat162float(fhi[j]));
    }
    size_t base = row * KLOG + e0;
    ((__nv_bfloat162*)(g_lA + base))[0]        = __nv_bfloat162(thi[0], thi[1]);
    ((__nv_bfloat162*)(g_lA + base))[1]        = __nv_bfloat162(thi[2], thi[3]);
    ((__nv_bfloat162*)(g_lA + base + 512))[0]  = __nv_bfloat162(tlo[0], tlo[1]);
    ((__nv_bfloat162*)(g_lA + base + 512))[1]  = __nv_bfloat162(tlo[2], tlo[3]);
    ((__nv_bfloat162*)(g_lA + base + 1024))[0] = __nv_bfloat162(thi[0], thi[1]);
    ((__nv_bfloat162*)(g_lA + base + 1024))[1] = __nv_bfloat162(thi[2], thi[3]);
    ((__nv_bfloat162*)(g_lB + base))[0]        = __nv_bfloat162(fhi[0], fhi[1]);
    ((__nv_bfloat162*)(g_lB + base))[1]        = __nv_bfloat162(fhi[2], fhi[3]);
    ((__nv_bfloat162*)(g_lB + base + 512))[0]  = __nv_bfloat162(fhi[0], fhi[1]);
    ((__nv_bfloat162*)(g_lB + base + 512))[1]  = __nv_bfloat162(fhi[2], fhi[3]);
    ((__nv_bfloat162*)(g_lB + base + 1024))[0] = __nv_bfloat162(flo[0], flo[1]);
    ((__nv_bfloat162*)(g_lB + base + 1024))[1] = __nv_bfloat162(flo[2], flo[3]);
}

// ---------------- kernel 6: logits HMMA GEMM: L[b] = lA[b] @ lB[b]^T (K=1536) ----------------
// 64 CTAs: b = tile>>2, p-half = (tile>>1)&1, q-half = tile&1. Output fp32 -> g_att.
__global__ __launch_bounds__(128, 2) void logits_gemm_kernel() {
    extern __shared__ __align__(1024) char smem[];
    const int t = blockIdx.x;
    const int b = t >> 2;
    const size_t rowA0 = (size_t)b * PP + (size_t)((t >> 1) & 1) * 128;  // global theta row
    const int q0 = (t & 1) << 7;                                          // q offset in row
    const size_t rowB0 = (size_t)b * PP + q0;
    const int nkb = KLOG >> 6;   // 24

    const int tid = threadIdx.x;
    const int lane = tid & 31, wid = tid >> 5;
    const uint32_t sbase = smem_u32(smem);
    const int chunk = tid & 7;
    const int lrow  = tid >> 3;

    const int m_off = (wid & 1) << 6;
    const int n_off = (wid >> 1) << 6;
    const int arow  = lane & 15;
    const int acolb = (lane >> 4) << 4;
    const int brow  = (lane & 7) + ((lane >> 4) << 3);
    const int bcolb = (lane & 8) << 1;

    auto load_stage = [&](int kb, int slot) {
        int k0 = kb << 6;
        uint32_t sb = sbase + slot * STAGE_BYTES;
#pragma unroll
        for (int rp = 0; rp < 8; ++rp) {
            int r = lrow + (rp << 4);
            int off = (r << 7) + (chunk << 4);
            int sw = off ^ ((off >> 3) & 0x70);
            cp_async16(sb + sw, g_lA + (rowA0 + r) * (size_t)KLOG + k0 + (chunk << 3));
            cp_async16(sb + 16384 + sw, g_lB + (rowB0 + r) * (size_t)KLOG + k0 + (chunk << 3));
        }
    };

    float acc[4][8][4];
#pragma unroll
    for (int i = 0; i < 4; ++i)
#pragma unroll
        for (int j = 0; j < 8; ++j)
#pragma unroll
            for (int q = 0; q < 4; ++q) acc[i][j][q] = 0.f;

    load_stage(0, 0); cp_commit();
    load_stage(1, 1); cp_commit();
    cp_wait<1>();
    __syncthreads();

    uint32_t afr[2][4][4], bfr[2][4][4];

    for (int kb = 0; kb < nkb; ++kb) {
        uint32_t sA = sbase + (kb % STAGES) * STAGE_BYTES;
        uint32_t sB = sA + 16384;
#pragma unroll
        for (int mt = 0; mt < 4; ++mt) {
            int off = ((m_off + (mt << 4) + arow) << 7) + acolb;
            ldsm_x4(afr[0][mt], sA + (off ^ ((off >> 3) & 0x70)));
        }
#pragma unroll
        for (int ntp = 0; ntp < 4; ++ntp) {
            int off = ((n_off + (ntp << 4) + brow) << 7) + bcolb;
            ldsm_x4(bfr[0][ntp], sB + (off ^ ((off >> 3) & 0x70)));
        }
        if (kb + 2 < nkb) load_stage(kb + 2, (kb + 2) % STAGES);
        cp_commit();

#pragma unroll
        for (int ks = 0; ks < 3; ++ks) {
            int nb = (ks + 1) & 1;
#pragma unroll
            for (int mt = 0; mt < 4; ++mt) {
                int off = ((m_off + (mt << 4) + arow) << 7) + ((ks + 1) << 5) + acolb;
                ldsm_x4(afr[nb][mt], sA + (off ^ ((off >> 3) & 0x70)));
            }
#pragma unroll
            for (int ntp = 0; ntp < 4; ++ntp) {
                int off = ((n_off + (ntp << 4) + brow) << 7) + ((ks + 1) << 5) + bcolb;
                ldsm_x4(bfr[nb][ntp], sB + (off ^ ((off >> 3) & 0x70)));
            }
            int cb = ks & 1;
#pragma unroll
            for (int mt = 0; mt < 4; ++mt)
#pragma unroll
                for (int nt = 0; nt < 8; ++nt)
                    mma16816(acc[mt][nt], afr[cb][mt], bfr[cb][nt >> 1] + ((nt & 1) << 1));
        }
        cp_wait<1>();
        __syncthreads();
#pragma unroll
        for (int mt = 0; mt < 4; ++mt)
#pragma unroll
            for (int nt = 0; nt < 8; ++nt)
                mma16816(acc[mt][nt], afr[1][mt], bfr[1][nt >> 1] + ((nt & 1) << 1));
    }

    // epilogue: logits fp32 -> g_att[(rowA)*256 + q0 + n]
#pragma unroll
    for (int mt = 0; mt < 4; ++mt) {
        size_t r0 = rowA0 + m_off + (mt << 4) + (lane >> 2);
#pragma unroll
        for (int nt = 0; nt < 8; ++nt) {
            int cix = q0 + n_off + (nt << 3) + ((lane & 3) << 1);
            *(float2*)(g_att + r0 * PP + cix) = make_float2(acc[mt][nt][0], acc[mt][nt][1]);
            *(float2*)(g_att + (r0 + 8) * PP + cix) = make_float2(acc[mt][nt][2], acc[mt][nt][3]);
        }
    }
}

// ---------------- kernel 7: softmax over rows of 256 ----------------
__global__ __launch_bounds__(256) void softmax_kernel() {
    int row = blockIdx.x, t = threadIdx.x;
    float v = g_att[(size_t)row * PP + t];
    float m = v;
#pragma unroll
    for (int o = 16; o; o >>= 1) m = fmaxf(m, __shfl_xor_sync(0xffffffffu, m, o));
    __shared__ float smax[8], ssum[8];
    if ((t & 31) == 0) smax[t >> 5] = m;
    __syncthreads();
    float M = smax[0];
#pragma unroll
    for (int i = 1; i < 8; ++i) M = fmaxf(M, smax[i]);
    float e = __expf(v - M);
    float s = e;
#pragma unroll
    for (int o = 16; o; o >>= 1) s += __shfl_xor_sync(0xffffffffu, s, o);
    if ((t & 31) == 0) ssum[t >> 5] = s;
    __syncthreads();
    float S = 0.f;
#pragma unroll
    for (int i = 0; i < 8; ++i) S += ssum[i];
    g_att[(size_t)row * PP + t] = e / S;
}

// ---------------- kernel 8: epilogue out = scale * w[b,p,n]*(g+g_b) + x ----------------
__global__ __launch_bounds__(256) void epilogue_kernel(const float* __restrict__ x,
                                                       const float* __restrict__ gb,
                                                       const float* __restrict__ scale,
                                                       float* __restrict__ out) {
    size_t i4 = (size_t)blockIdx.x * 256 + threadIdx.x;
    size_t e0 = i4 << 2;
    int wq = (int)(e0 & 255);
    int h  = (int)((e0 >> 8) & 255);
    int c  = (int)((e0 >> 16) & 15);
    int b  = (int)(e0 >> 20);
    int pi = h >> 4, ih = h & 15, pj = wq >> 4, iw = wq & 15;
    int p = (pi << 4) + pj;
    int n = (ih << 4) + iw;
    size_t rowbp = (size_t)b * PP + p;
    float4 wv = *(const float4*)(g_att + rowbp * PP + n);
    __nv_bfloat162 gv01 = ((const __nv_bfloat162*)(g_gm_bf + rowbp * DD + (c << 8) + n))[0];
    __nv_bfloat162 gv23 = ((const __nv_bfloat162*)(g_gm_bf + rowbp * DD + (c << 8) + n))[1];
    float4 gbv = *(const float4*)(gb + (c << 8) + n);
    float4 xv = *(const float4*)(x + e0);
    float s = scale[0];
    float4 o;
    o.x = s * wv.x * (__bfloat162float(gv01.x) + gbv.x) + xv.x;
    o.y = s * wv.y * (__bfloat162float(gv01.y) + gbv.y) + xv.y;
    o.z = s * wv.z * (__bfloat162float(gv23.x) + gbv.z) + xv.z;
    o.w = s * wv.w * (__bfloat162float(gv23.y) + gbv.w) + xv.w;
    *(float4*)(out + e0) = o;
}

// ---------------- launcher ----------------
extern "C" void kernel_launch(void* const* d_in, const int* in_sizes, int n_in,
                              void* d_out, int out_size) {
    (void)in_sizes; (void)n_in; (void)out_size;
    const float* x       = (const float*)d_in[0];
    const float* theta_w = (const float*)d_in[1];
    const float* theta_b = (const float*)d_in[2];
    const float* f_w     = (const float*)d_in[3];
    const float* f_b     = (const float*)d_in[4];
    const float* gw      = (const float*)d_in[5];
    const float* gb      = (const float*)d_in[6];
    const float* scale   = (const float*)d_in[7];
    float* out = (float*)d_out;

    cudaFuncSetAttribute(gemm_hmma_kernel,
                         cudaFuncAttributeMaxDynamicSharedMemorySize, GEMM_SMEM);
    cudaFuncSetAttribute(logits_gemm_kernel,
                         cudaFuncAttributeMaxDynamicSharedMemorySize, GEMM_SMEM);

    prep_kernel<<<16384, 256>>>(x);                         // also resets g_tile_ctr
    wsplit1_kernel<<<dim3(128, 32), dim3(32, 32)>>>(theta_w, f_w);
    wsplit2_kernel<<<dim3(128, 128), dim3(32, 32)>>>(gw);
    gemm_hmma_kernel<<<304, 128, GEMM_SMEM>>>();            // persistent, dynamic tiles
    tfsplit_kernel<<<2048, 256>>>(theta_b, f_b);            // theta/f hi/lo (+bias)
    logits_gemm_kernel<<<64, 128, GEMM_SMEM>>>();           // logits on tensor cores
    softmax_kernel<<<4096, 256>>>();
    epilogue_kernel<<<16384, 256>>>(x, gb, scale, out);
}